// round 3
// baseline (speedup 1.0000x reference)
#include <cuda_runtime.h>

// Problem constants
#define T_   24      // HIST
#define D_   256     // SKIP
#define E_   128     // END
#define O_   2       // OUT_DIM
#define KK   13      // KERNEL
#define F_   12      // future steps
#define NB   4096    // B*N nodes

#define THREADS 128
#define DC      32                 // d-chunk size for W1 staging
#define WROWQ   9                  // ws row stride in float4 (32 j + 4 pad floats)
#define XROWQ   65                 // xs row stride in float4 (256 d + 4 pad floats)
#define HROW    132                // h row stride in floats

typedef unsigned long long u64;

__device__ __forceinline__ void fma2(u64 &d, u64 a, u64 b) {
    // packed f32x2 fma: d.lo += a.lo*b.lo ; d.hi += a.hi*b.hi
    asm("fma.rn.f32x2 %0, %1, %2, %0;" : "+l"(d) : "l"(a), "l"(b));
}
__device__ __forceinline__ void unpack2(u64 v, float &lo, float &hi) {
    asm("mov.b64 {%0, %1}, %2;" : "=f"(lo), "=f"(hi) : "l"(v));
}

__global__ __launch_bounds__(THREADS, 4)
void tcnn_moe_kernel(const float* __restrict__ x,
                     const int*   __restrict__ labels,
                     const float* __restrict__ W1,
                     const float* __restrict__ b1,
                     const float* __restrict__ W2,
                     const float* __restrict__ b2,
                     float*       __restrict__ out)
{
    __shared__ float4 xs4[T_ * XROWQ];   // 24.96 KB: relu(x); later aliased as h
    __shared__ float4 ws4[E_ * WROWQ];   // 18.4 KB: W1 chunk, NATURAL [e][j] layout
    __shared__ float  red[4 * 24];       // cross-warp reduction for layer 2

    const int node = blockIdx.x;
    const int tid  = threadIdx.x;
    const int lane = tid & 31;
    const int warp = tid >> 5;            // 0..3
    const int lbl  = labels[node];        // expert id 0..7

    // ---------------- stage relu(x) into padded smem (coalesced float4) ----------------
    {
        const float4* xg = reinterpret_cast<const float4*>(x + (size_t)node * (T_ * D_));
        #pragma unroll
        for (int k = 0; k < (T_ * D_ / 4) / THREADS; k++) {   // 12 iters
            int idx = tid + k * THREADS;          // float4 index in (t, d/4)
            int t   = idx >> 6;                   // 64 float4 per row
            int dq  = idx & 63;
            float4 v = xg[idx];
            v.x = fmaxf(v.x, 0.f); v.y = fmaxf(v.y, 0.f);
            v.z = fmaxf(v.z, 0.f); v.w = fmaxf(v.w, 0.f);
            xs4[t * XROWQ + dq] = v;
        }
    }

    // ---------------- layer 1: h[t][e] = relu(b1[e] + sum_d xr[t][d]*W1[e][d]) ----
    // 128 threads: tg = lane>>2 owns t in {3tg..3tg+2}; warp*32 + (lane&3)*8 = e0 owns 8 e.
    // acc[i][r] is a packed u64: {sum over even j, sum over odd j} for (t0+i, e0+r).
    u64 acc[3][8];
    #pragma unroll
    for (int i = 0; i < 3; i++)
        #pragma unroll
        for (int r = 0; r < 8; r++) acc[i][r] = 0ull;

    const float4* W1g4 = reinterpret_cast<const float4*>(W1 + (size_t)lbl * (E_ * D_));
    const int t0 = (lane >> 2) * 3;
    const int e0 = warp * 32 + (lane & 3) * 8;

    for (int d0q = 0; d0q < D_ / 4; d0q += DC / 4) {       // chunk = 8 float4 of d
        __syncthreads();
        // stage W1 chunk in natural [e][j] layout: float4 STS, conflict-free phases
        #pragma unroll
        for (int k = 0; k < (DC * E_ / 4) / THREADS; k++) {  // 8 iters
            int q  = tid + k * THREADS;        // 0..1023
            int e  = q >> 3;                   // 8 float4 per e-row
            int jq = q & 7;
            ws4[e * WROWQ + jq] = W1g4[e * (D_ / 4) + d0q + jq];
        }
        __syncthreads();

        #pragma unroll
        for (int jq = 0; jq < DC / 4; jq++) {
            // x: 3 rows, one LDS.128 each (8 distinct t per warp, bcast over eq)
            ulonglong2 xv0 = *reinterpret_cast<const ulonglong2*>(&xs4[(t0    ) * XROWQ + d0q + jq]);
            ulonglong2 xv1 = *reinterpret_cast<const ulonglong2*>(&xs4[(t0 + 1) * XROWQ + d0q + jq]);
            ulonglong2 xv2 = *reinterpret_cast<const ulonglong2*>(&xs4[(t0 + 2) * XROWQ + d0q + jq]);
            #pragma unroll
            for (int r = 0; r < 8; r++) {
                ulonglong2 wv = *reinterpret_cast<const ulonglong2*>(&ws4[(e0 + r) * WROWQ + jq]);
                fma2(acc[0][r], xv0.x, wv.x);  fma2(acc[0][r], xv0.y, wv.y);
                fma2(acc[1][r], xv1.x, wv.x);  fma2(acc[1][r], xv1.y, wv.y);
                fma2(acc[2][r], xv2.x, wv.x);  fma2(acc[2][r], xv2.y, wv.y);
            }
        }
    }

    __syncthreads();   // all warps done reading xs -> safe to alias as h

    // bias + relu, h[t][e] = relu(lo+hi+b1[e]); store to smem (alias of xs4)
    float* hs = reinterpret_cast<float*>(xs4);
    {
        const float* b1g = b1 + lbl * E_;
        float bb[8];
        #pragma unroll
        for (int r = 0; r < 8; r++) bb[r] = b1g[e0 + r];
        #pragma unroll
        for (int i = 0; i < 3; i++) {
            float hv[8];
            #pragma unroll
            for (int r = 0; r < 8; r++) {
                float lo, hi;
                unpack2(acc[i][r], lo, hi);
                hv[r] = fmaxf(lo + hi + bb[r], 0.f);
            }
            float4* dst = reinterpret_cast<float4*>(hs + (t0 + i) * HROW + e0);
            dst[0] = make_float4(hv[0], hv[1], hv[2], hv[3]);
            dst[1] = make_float4(hv[4], hv[5], hv[6], hv[7]);
        }
    }
    __syncthreads();

    // ---------------- layer 2: out[f][o] = b2[o] + sum_{k,e} h[f+k][e]*W2[o][e][k] ----
    {
        const int e = tid;   // 0..127
        float hreg[T_];
        #pragma unroll
        for (int t = 0; t < T_; t++) hreg[t] = hs[t * HROW + e];

        const float* W2g = W2 + (size_t)lbl * (O_ * E_ * KK);
        #pragma unroll
        for (int o = 0; o < O_; o++) {
            float w2r[KK];
            #pragma unroll
            for (int k = 0; k < KK; k++) w2r[k] = W2g[(o * E_ + e) * KK + k];

            float accf[F_];
            #pragma unroll
            for (int f = 0; f < F_; f++) {
                float s = 0.f;
                #pragma unroll
                for (int k = 0; k < KK; k++) s = fmaf(hreg[f + k], w2r[k], s);
                accf[f] = s;
            }
            #pragma unroll
            for (int f = 0; f < F_; f++) {
                float s = accf[f];
                #pragma unroll
                for (int off = 16; off > 0; off >>= 1)
                    s += __shfl_xor_sync(0xffffffffu, s, off);
                if (lane == 0) red[warp * 24 + f * 2 + o] = s;
            }
        }
    }
    __syncthreads();

    if (tid < 24) {   // tid = f*2 + o
        int o = tid & 1;
        float s = red[tid] + red[24 + tid] + red[48 + tid] + red[72 + tid];
        s += b2[lbl * O_ + o];
        out[(size_t)node * (F_ * O_) + tid] = s;
    }
}

extern "C" void kernel_launch(void* const* d_in, const int* in_sizes, int n_in,
                              void* d_out, int out_size) {
    const float* x      = (const float*)d_in[0];   // (8,512,24,256) f32
    const int*   labels = (const int*)  d_in[1];   // (8,512) i32
    const float* W1     = (const float*)d_in[2];   // (8,128,256)
    const float* b1     = (const float*)d_in[3];   // (8,128)
    const float* W2     = (const float*)d_in[4];   // (8,2,128,13)
    const float* b2     = (const float*)d_in[5];   // (8,2)
    float* out = (float*)d_out;                    // (8,512,12,2) f32

    tcnn_moe_kernel<<<NB, THREADS>>>(x, labels, W1, b1, W2, b2, out);
}

// round 6
// speedup vs baseline: 2.3565x; 2.3565x over previous
#include <cuda_runtime.h>

// Problem constants
#define T_   24      // HIST
#define D_   256     // SKIP
#define E_   128     // END
#define O_   2       // OUT_DIM
#define KK   13      // KERNEL
#define F_   12      // future steps
#define NB   4096    // B*N nodes

#define THREADS 256
#define DC      32   // d-chunk (floats) per staging round = 8 float4
#define WROWQ   9    // ws row stride in float4 (8 data + 1 pad = 144B)

typedef unsigned long long u64;

__device__ __forceinline__ void fma2(u64 &d, u64 a, u64 b) {
    // packed f32x2 fma: d.lo += a.lo*b.lo ; d.hi += a.hi*b.hi
    asm("fma.rn.f32x2 %0, %1, %2, %0;" : "+l"(d) : "l"(a), "l"(b));
}
__device__ __forceinline__ void unpack2(u64 v, float &lo, float &hi) {
    asm("mov.b64 {%0, %1}, %2;" : "=f"(lo), "=f"(hi) : "l"(v));
}

__global__ __launch_bounds__(THREADS, 3)
void tcnn_moe_kernel(const float* __restrict__ x,
                     const int*   __restrict__ labels,
                     const float* __restrict__ W1,
                     const float* __restrict__ b1,
                     const float* __restrict__ W2,
                     const float* __restrict__ b2,
                     float*       __restrict__ out)
{
    __shared__ float4 xs4[T_ * (D_ / 4)];   // 24 KB: relu(x), natural layout; aliased as h later
    __shared__ float4 ws4[E_ * WROWQ];      // 18.4 KB: W1 chunk, natural [e][jq] + rotation swizzle
    __shared__ float  red[4 * 24];          // cross-warp reduction for layer 2

    const int node = blockIdx.x;
    const int tid  = threadIdx.x;
    const int lane = tid & 31;
    const int warp = tid >> 5;            // 0..7
    const int lbl  = labels[node];        // expert id 0..7

    // ---------------- stage relu(x) into smem (coalesced float4, natural layout) ----------
    {
        const float4* xg = reinterpret_cast<const float4*>(x + (size_t)node * (T_ * D_));
        #pragma unroll
        for (int i = 0; i < (T_ * D_ / 4) / THREADS; i++) {   // 6 iters
            int idx = tid + i * THREADS;
            float4 v = xg[idx];
            v.x = fmaxf(v.x, 0.f); v.y = fmaxf(v.y, 0.f);
            v.z = fmaxf(v.z, 0.f); v.w = fmaxf(v.w, 0.f);
            xs4[idx] = v;
        }
    }

    // ---------------- layer 1: h[t][e] = relu(b1[e] + sum_d xr[t][d]*W1[e][d]) ----
    // warp w owns t in {3w,3w+1,3w+2}; lane owns e in [4*lane, 4*lane+4).
    // acc[i][r]: packed {sum over even j, sum over odd j} for (t0+i, 4*lane+r).
    u64 acc[3][4];
    #pragma unroll
    for (int i = 0; i < 3; i++)
        #pragma unroll
        for (int r = 0; r < 4; r++) acc[i][r] = 0ull;

    const float4* W1g4 = reinterpret_cast<const float4*>(W1 + (size_t)lbl * (E_ * D_));
    const int t0  = warp * 3;
    const int e0  = lane * 4;
    const int rot = (lane >> 1) & 7;      // = (e>>3)&7 for all 4 of this lane's e rows

    for (int d0q = 0; d0q < D_ / 4; d0q += DC / 4) {     // 8 chunks of 8 float4
        __syncthreads();
        // stage W1 chunk, natural [e][jq] with column rotation:
        // physical col = (jq + (e>>3)) & 7  -> both STS and compute reads hit 4-wf floor.
        #pragma unroll
        for (int k = 0; k < (DC * E_ / 4) / THREADS; k++) {  // 4 iters
            int q   = tid + k * THREADS;     // 0..1023
            int e   = q >> 3;
            int jq  = q & 7;
            int col = (jq + ((e >> 3) & 7)) & 7;
            ws4[e * WROWQ + col] = W1g4[e * (D_ / 4) + d0q + jq];
        }
        __syncthreads();

        #pragma unroll
        for (int jq = 0; jq < DC / 4; jq++) {
            // x: 3 warp-uniform float4 broadcasts (1 wf each)
            const int xi = d0q + jq;
            float4 xv0 = xs4[(t0    ) * (D_ / 4) + xi];
            float4 xv1 = xs4[(t0 + 1) * (D_ / 4) + xi];
            float4 xv2 = xs4[(t0 + 2) * (D_ / 4) + xi];
            u64 x0a = *reinterpret_cast<u64*>(&xv0.x), x0b = *reinterpret_cast<u64*>(&xv0.z);
            u64 x1a = *reinterpret_cast<u64*>(&xv1.x), x1b = *reinterpret_cast<u64*>(&xv1.z);
            u64 x2a = *reinterpret_cast<u64*>(&xv2.x), x2b = *reinterpret_cast<u64*>(&xv2.z);

            const int col = (jq + rot) & 7;
            #pragma unroll
            for (int r = 0; r < 4; r++) {
                float4 wv = ws4[(e0 + r) * WROWQ + col];
                u64 wa = *reinterpret_cast<u64*>(&wv.x);
                u64 wb = *reinterpret_cast<u64*>(&wv.z);
                fma2(acc[0][r], x0a, wa);  fma2(acc[0][r], x0b, wb);
                fma2(acc[1][r], x1a, wa);  fma2(acc[1][r], x1b, wb);
                fma2(acc[2][r], x2a, wa);  fma2(acc[2][r], x2b, wb);
            }
        }
    }

    __syncthreads();   // all warps done reading xs -> safe to alias as hs

    // bias + relu: h = relu(lo + hi + b1[e]); store to smem (alias of xs4)
    float* hs = reinterpret_cast<float*>(xs4);   // hs[t*128 + e]
    {
        float4 bb = *reinterpret_cast<const float4*>(b1 + lbl * E_ + e0);
        float bba[4] = {bb.x, bb.y, bb.z, bb.w};
        #pragma unroll
        for (int i = 0; i < 3; i++) {
            float hv[4];
            #pragma unroll
            for (int r = 0; r < 4; r++) {
                float lo, hi;
                unpack2(acc[i][r], lo, hi);
                hv[r] = fmaxf(lo + hi + bba[r], 0.f);
            }
            *reinterpret_cast<float4*>(hs + (t0 + i) * E_ + e0) =
                make_float4(hv[0], hv[1], hv[2], hv[3]);
        }
    }
    __syncthreads();

    // ---------------- layer 2: out[f][o] = b2[o] + sum_{k,e} h[f+k][e]*W2[o][e][k] ----
    if (warp < 4) {
        const int e = tid;   // 0..127
        float hreg[T_];
        #pragma unroll
        for (int t = 0; t < T_; t++) hreg[t] = hs[t * E_ + e];

        const float* W2g = W2 + (size_t)lbl * (O_ * E_ * KK);
        #pragma unroll
        for (int o = 0; o < O_; o++) {
            float w2r[KK];
            #pragma unroll
            for (int k = 0; k < KK; k++) w2r[k] = W2g[(o * E_ + e) * KK + k];

            float accf[F_];
            #pragma unroll
            for (int f = 0; f < F_; f++) {
                float s = 0.f;
                #pragma unroll
                for (int k = 0; k < KK; k++) s = fmaf(hreg[f + k], w2r[k], s);
                accf[f] = s;
            }
            #pragma unroll
            for (int f = 0; f < F_; f++) {
                float s = accf[f];
                #pragma unroll
                for (int off = 16; off > 0; off >>= 1)
                    s += __shfl_xor_sync(0xffffffffu, s, off);
                if (lane == 0) red[warp * 24 + f * 2 + o] = s;
            }
        }
    }
    __syncthreads();

    if (tid < 24) {   // tid = f*2 + o
        int o = tid & 1;
        float s = red[tid] + red[24 + tid] + red[48 + tid] + red[72 + tid];
        s += b2[lbl * O_ + o];
        out[(size_t)node * (F_ * O_) + tid] = s;
    }
}

extern "C" void kernel_launch(void* const* d_in, const int* in_sizes, int n_in,
                              void* d_out, int out_size) {
    const float* x      = (const float*)d_in[0];   // (8,512,24,256) f32
    const int*   labels = (const int*)  d_in[1];   // (8,512) i32
    const float* W1     = (const float*)d_in[2];   // (8,128,256)
    const float* b1     = (const float*)d_in[3];   // (8,128)
    const float* W2     = (const float*)d_in[4];   // (8,2,128,13)
    const float* b2     = (const float*)d_in[5];   // (8,2)
    float* out = (float*)d_out;                    // (8,512,12,2) f32

    tcnn_moe_kernel<<<NB, THREADS>>>(x, labels, W1, b1, W2, b2, out);
}